// round 5
// baseline (speedup 1.0000x reference)
#include <cuda_runtime.h>
#include <cuda_fp16.h>

#define NN 100000
#define NE 1600000
#define CSRB 592                       // persistent CSR kernel blocks (148*4, resident)
#define CHUNK ((NN + CSRB - 1) / CSRB) // 169 nodes per block (<=256)

// ---------------- scratch (static __device__, no allocs) ----------------
struct Zeroed {
    int cnt[NN];        // hist counts
    int cur[NN];        // fill cursors
    float stats[256];   // layer1 sum/sumsq [0:128), layer2 [128:256)
    unsigned bar;       // grid barrier counter
};
__device__ Zeroed g_z;

__device__ __half g_h16[NN * 64];       // GEMM output (pre-aggregate), fp16
__device__ float  g_agg[NN * 64];       // aggregated output, fp32
__device__ int2   g_edges[NE];          // CSR payload: {src, __float_as_int(edge_norm)}
__device__ int    g_rowptr[NN + 1];
__device__ float  g_dis[NN];
__device__ float  g_selfnorm[NN];
__device__ int    g_bsum[CSRB];

// ---------------- helpers ----------------
__device__ __forceinline__ unsigned f2tf32(float x) {
    unsigned r;
    asm("cvt.rna.tf32.f32 %0, %1;" : "=r"(r) : "f"(x));
    return r;
}

__device__ __forceinline__ void mma_tf32(float* d, const unsigned* a, const unsigned* b) {
    asm volatile(
        "mma.sync.aligned.m16n8k8.row.col.f32.tf32.tf32.f32 "
        "{%0,%1,%2,%3}, {%4,%5,%6,%7}, {%8,%9}, {%0,%1,%2,%3};"
        : "+f"(d[0]), "+f"(d[1]), "+f"(d[2]), "+f"(d[3])
        : "r"(a[0]), "r"(a[1]), "r"(a[2]), "r"(a[3]), "r"(b[0]), "r"(b[1]));
}

__device__ __forceinline__ void cp16(void* smem, const void* gmem) {
    unsigned s = (unsigned)__cvta_generic_to_shared(smem);
    asm volatile("cp.async.ca.shared.global [%0], [%1], 16;" :: "r"(s), "l"(gmem));
}

__device__ __forceinline__ int edge_idx(const void* ei, int i, int is64) {
    return is64 ? (int)((const long long*)ei)[i] : ((const int*)ei)[i];
}

// per-block int64-layout detect (node ids < 2^31: int64 => odd words all zero)
__device__ __forceinline__ int block_is64(const void* ei) {
    __shared__ int s_is64;
    if (threadIdx.x < 32) {
        const int* p = (const int*)ei;
        int nz = p[2 * threadIdx.x + 1] != 0;
        unsigned m = __ballot_sync(0xffffffffu, nz);
        if (threadIdx.x == 0) s_is64 = (m == 0);
    }
    __syncthreads();
    return s_is64;
}

// software grid barrier (all CSRB blocks resident)
__device__ __forceinline__ void gridbar(unsigned goal) {
    __syncthreads();
    if (threadIdx.x == 0) {
        __threadfence();
        atomicAdd(&g_z.bar, 1u);
        while (*(volatile unsigned*)&g_z.bar < goal) { }
        __threadfence();
    }
    __syncthreads();
}

// ---------------- fused CSR build: hist -> scan+init -> fill ----------------
__global__ __launch_bounds__(256, 4) void k_csr(const void* ei) {
    int is64 = block_is64(ei);
    int tid = threadIdx.x;
    int b = blockIdx.x;
    __shared__ int sh[256];
    __shared__ int s_off;

    // phase 1: degree histogram (grid-stride)
    for (int e = b * 256 + tid; e < NE; e += CSRB * 256)
        atomicAdd(&g_z.cnt[edge_idx(ei, NE + e, is64)], 1);
    gridbar(CSRB);

    // phase 2a: per-block chunk sum
    int base = b * CHUNK;
    int len = NN - base;
    if (len < 0) len = 0;
    if (len > CHUNK) len = CHUNK;
    int v = (tid < len) ? g_z.cnt[base + tid] : 0;
    sh[tid] = v;
    __syncthreads();
#pragma unroll
    for (int off = 128; off > 0; off >>= 1) {
        if (tid < off) sh[tid] += sh[tid + off];
        __syncthreads();
    }
    if (tid == 0) g_bsum[b] = sh[0];
    gridbar(2 * CSRB);

    // phase 2b: block offset = sum of g_bsum[0..b)
    int part = 0;
    for (int j = tid; j < b; j += 256) part += g_bsum[j];
    __syncthreads();
    sh[tid] = part;
    __syncthreads();
#pragma unroll
    for (int off = 128; off > 0; off >>= 1) {
        if (tid < off) sh[tid] += sh[tid + off];
        __syncthreads();
    }
    if (tid == 0) s_off = sh[0];
    __syncthreads();
    int blockoff = s_off;

    // in-block inclusive scan of chunk (Hillis-Steele over 256 slots)
    sh[tid] = v;
    __syncthreads();
#pragma unroll
    for (int off = 1; off < 256; off <<= 1) {
        int x = (tid >= off) ? sh[tid - off] : 0;
        __syncthreads();
        sh[tid] += x;
        __syncthreads();
    }
    if (tid < len) {
        int gid = base + tid;
        g_rowptr[gid] = blockoff + sh[tid] - v;   // exclusive
        float deg = (float)v + 1.0f;
        g_dis[gid] = rsqrtf(deg);
        g_selfnorm[gid] = 1.0f / deg;
    }
    if (b == 0 && tid == 0) g_rowptr[NN] = NE;
    gridbar(3 * CSRB);

    // phase 3: fill CSR (grid-stride)
    for (int e = b * 256 + tid; e < NE; e += CSRB * 256) {
        int s = edge_idx(ei, e, is64);
        int d = edge_idx(ei, NE + e, is64);
        int pos = g_rowptr[d] + atomicAdd(&g_z.cur[d], 1);
        float w = g_dis[s] * g_dis[d];
        g_edges[pos] = make_int2(s, __float_as_int(w));
    }
}

// ---------------- tf32 MMA GEMM with cp.async pipelined A staging ----------------
// out = act(A) @ W + bias, fp16 out. N = NT*8. Block: 128 rows x N, 256 threads (8 warps).
// BN=1: BN affine from g_z.stats[soff]+gamma/beta computed in prologue, applied at
// fragment-load time (A staged as raw fp32).
template <int K, int NT, int BN, int STAGES>
__global__ __launch_bounds__(256) void k_gemm(const float* __restrict__ A,
                                              const float* __restrict__ W,
                                              const float* __restrict__ bias,
                                              __half* __restrict__ out,
                                              const float* __restrict__ gamma,
                                              const float* __restrict__ beta,
                                              int soff) {
    constexpr int N = NT * 8;
    constexpr int NK8 = K / 8;
    __shared__ __align__(16) unsigned Bp[NK8 * NT * 64];  // [kstep][ntile][lane][2]
    __shared__ __align__(16) float As[STAGES][128 * 12];  // row stride 12 (48B, conflict-free)
    __shared__ float sA[64], sB[64];

    int tid = threadIdx.x;
    int lane = tid & 31;
    int warp = tid >> 5;

    // permute + convert W into exact B-fragment layout
    for (int i = tid; i < NK8 * NT * 32; i += 256) {
        int l = i & 31;
        int t = (i >> 5) % NT;
        int ks = i / (32 * NT);
        int kk = ks * 8 + (l & 3);
        int n = t * 8 + (l >> 2);
        Bp[i * 2 + 0] = f2tf32(W[kk * N + n]);
        Bp[i * 2 + 1] = f2tf32(W[(kk + 4) * N + n]);
    }
    if (BN) {
        if (tid < 64) {
            float mu = g_z.stats[soff + tid] * (1.0f / NN);
            float var = g_z.stats[soff + 64 + tid] * (1.0f / NN) - mu * mu;
            float a = gamma[tid] * rsqrtf(var + 1e-5f);
            sA[tid] = a;
            sB[tid] = beta[tid] - mu * a;
        }
    }

    float acc[NT][4];
#pragma unroll
    for (int t = 0; t < NT; t++)
#pragma unroll
        for (int j = 0; j < 4; j++) acc[t][j] = 0.f;

    int m0 = blockIdx.x * 128;
    // thread -> one 16B chunk per stage: row = tid>>1, half = tid&1
    int srow = tid >> 1;
    int shalf = tid & 1;
    int sm = m0 + srow;
    if (sm > NN - 1) sm = NN - 1;
    const float* sbase = A + (size_t)sm * K + shalf * 4;
    float* sdst0 = &As[0][srow * 12 + shalf * 4];

    __syncthreads();   // Bp/sA/sB ready

    // prologue: stages 0..STAGES-2
#pragma unroll
    for (int s = 0; s < STAGES - 1; s++) {
        cp16(&As[s][srow * 12 + shalf * 4], sbase + s * 8);
        asm volatile("cp.async.commit_group;");
    }

    for (int ks = 0; ks < NK8; ks++) {
        asm volatile("cp.async.wait_group %0;" :: "n"(STAGES - 2));
        __syncthreads();
        // issue stage ks+STAGES-1 (writes the stage all threads just finished)
        int nxt = ks + STAGES - 1;
        if (nxt < NK8)
            cp16(sdst0 + (nxt % STAGES) * 128 * 12, sbase + nxt * 8);
        asm volatile("cp.async.commit_group;");

        // compute stage ks
        const float* as = As[ks % STAGES];
        int r = warp * 16 + (lane >> 2);
        int cc = lane & 3;
        float f0 = as[r * 12 + cc];
        float f1 = as[(r + 8) * 12 + cc];
        float f2 = as[r * 12 + cc + 4];
        float f3 = as[(r + 8) * 12 + cc + 4];
        if (BN) {
            int k = ks * 8;
            float a0 = sA[k + cc], b0 = sB[k + cc];
            float a1 = sA[k + cc + 4], b1 = sB[k + cc + 4];
            f0 = fmaxf(fmaf(f0, a0, b0), 0.f);
            f1 = fmaxf(fmaf(f1, a0, b0), 0.f);
            f2 = fmaxf(fmaf(f2, a1, b1), 0.f);
            f3 = fmaxf(fmaf(f3, a1, b1), 0.f);
        }
        unsigned a[4] = { f2tf32(f0), f2tf32(f1), f2tf32(f2), f2tf32(f3) };
        const unsigned* bp = &Bp[ks * NT * 64 + lane * 2];
#pragma unroll
        for (int t = 0; t < NT; t++) {
            unsigned bb[2] = { bp[t * 64], bp[t * 64 + 1] };
            mma_tf32(acc[t], a, bb);
        }
    }

    // epilogue: c0,c1 at (r, col..col+1); c2,c3 at (r+8, col..col+1); pack to half2
    int r0 = m0 + warp * 16 + (lane >> 2);
    int c0 = (lane & 3) * 2;
#pragma unroll
    for (int t = 0; t < NT; t++) {
        int col = t * 8 + c0;
        float2 bv = *(const float2*)(bias + col);
        if (r0 < NN) {
            __half2 o = __floats2half2_rn(acc[t][0] + bv.x, acc[t][1] + bv.y);
            *(__half2*)(out + (size_t)r0 * N + col) = o;
        }
        if (r0 + 8 < NN) {
            __half2 o = __floats2half2_rn(acc[t][2] + bv.x, acc[t][3] + bv.y);
            *(__half2*)(out + (size_t)(r0 + 8) * N + col) = o;
        }
    }
}

// ---------------- aggregate (+ fused BN stats): grid-stride warp-per-node ----------------
// h fp16: lane l covers channels 2l, 2l+1. SOFF>=0: accumulate sum/sumsq into g_z.stats[SOFF].
template <int C, int SOFF>
__global__ __launch_bounds__(256) void k_aggregate(const __half* __restrict__ h,
                                                   float* __restrict__ out) {
    constexpr int C2 = C / 2;
    int lane = threadIdx.x & 31;
    int wid = threadIdx.x >> 5;
    int warpG = blockIdx.x * 8 + wid;
    int nwarp = gridDim.x * 8;
    const __half2* h2 = (const __half2*)h;
    const bool act = (lane < C2);
    float ts0 = 0.f, ts1 = 0.f, tq0 = 0.f, tq1 = 0.f;

    for (int n = warpG; n < NN; n += nwarp) {
        int beg = g_rowptr[n];
        int end = g_rowptr[n + 1];
        float a0 = 0.f, a1 = 0.f;
        int e = beg;
        for (; e + 3 < end; e += 4) {       // 4-edge unroll for MLP
            int2 e0 = g_edges[e];
            int2 e1 = g_edges[e + 1];
            int2 e2 = g_edges[e + 2];
            int2 e3 = g_edges[e + 3];
            if (act) {
                float2 v0 = __half22float2(h2[(size_t)e0.x * C2 + lane]);
                float2 v1 = __half22float2(h2[(size_t)e1.x * C2 + lane]);
                float2 v2 = __half22float2(h2[(size_t)e2.x * C2 + lane]);
                float2 v3 = __half22float2(h2[(size_t)e3.x * C2 + lane]);
                float w0 = __int_as_float(e0.y), w1 = __int_as_float(e1.y);
                float w2 = __int_as_float(e2.y), w3 = __int_as_float(e3.y);
                a0 = fmaf(w0, v0.x, a0); a1 = fmaf(w0, v0.y, a1);
                a0 = fmaf(w1, v1.x, a0); a1 = fmaf(w1, v1.y, a1);
                a0 = fmaf(w2, v2.x, a0); a1 = fmaf(w2, v2.y, a1);
                a0 = fmaf(w3, v3.x, a0); a1 = fmaf(w3, v3.y, a1);
            }
        }
        for (; e < end; e++) {
            int2 ed = g_edges[e];
            if (act) {
                float w = __int_as_float(ed.y);
                float2 v = __half22float2(h2[(size_t)ed.x * C2 + lane]);
                a0 = fmaf(w, v.x, a0);
                a1 = fmaf(w, v.y, a1);
            }
        }
        if (act) {
            float sn = g_selfnorm[n];
            float2 vs = __half22float2(h2[(size_t)n * C2 + lane]);
            a0 = fmaf(sn, vs.x, a0);
            a1 = fmaf(sn, vs.y, a1);
            float2 o = { a0, a1 };
            *(float2*)(out + (size_t)n * C + 2 * lane) = o;
            if (SOFF >= 0) {
                ts0 += a0;
                ts1 += a1;
                tq0 = fmaf(a0, a0, tq0);
                tq1 = fmaf(a1, a1, tq1);
            }
        }
    }

    if (SOFF >= 0) {
        __shared__ float sm[4][256];
        sm[0][threadIdx.x] = ts0;
        sm[1][threadIdx.x] = ts1;
        sm[2][threadIdx.x] = tq0;
        sm[3][threadIdx.x] = tq1;
        __syncthreads();
        if (threadIdx.x < 32) {
            int l = threadIdx.x;
            float s0 = 0.f, s1 = 0.f, q0 = 0.f, q1 = 0.f;
#pragma unroll
            for (int w = 0; w < 8; w++) {
                s0 += sm[0][w * 32 + l];
                s1 += sm[1][w * 32 + l];
                q0 += sm[2][w * 32 + l];
                q1 += sm[3][w * 32 + l];
            }
            atomicAdd(&g_z.stats[SOFF + 2 * l], s0);
            atomicAdd(&g_z.stats[SOFF + 2 * l + 1], s1);
            atomicAdd(&g_z.stats[SOFF + 64 + 2 * l], q0);
            atomicAdd(&g_z.stats[SOFF + 64 + 2 * l + 1], q1);
        }
    }
}

// ---------------- launch ----------------
extern "C" void kernel_launch(void* const* d_in, const int* in_sizes, int n_in,
                              void* d_out, int out_size) {
    const float* x  = (const float*)d_in[0];
    const void*  ei = d_in[1];
    const float* W1 = (const float*)d_in[2];
    const float* b1 = (const float*)d_in[3];
    const float* g1 = (const float*)d_in[4];
    const float* be1 = (const float*)d_in[5];
    const float* W2 = (const float*)d_in[6];
    const float* b2 = (const float*)d_in[7];
    const float* g2 = (const float*)d_in[8];
    const float* be2 = (const float*)d_in[9];
    const float* W3 = (const float*)d_in[10];
    const float* b3 = (const float*)d_in[11];
    float* out = (float*)d_out;

    __half* h = nullptr;
    float* agg = nullptr;
    void* p_z = nullptr;
    cudaGetSymbolAddress((void**)&h, g_h16);
    cudaGetSymbolAddress((void**)&agg, g_agg);
    cudaGetSymbolAddress(&p_z, g_z);

    const int GB = (NN + 127) / 128;          // 782
    const int AGB = 1184;                     // grid-stride aggregate blocks

    cudaMemsetAsync(p_z, 0, sizeof(Zeroed));  // counters + cursors + stats + barrier

    k_csr<<<CSRB, 256>>>(ei);                                              // 1
    k_gemm<128, 8, 0, 2><<<GB, 256>>>(x, W1, b1, h, nullptr, nullptr, 0);  // 2
    k_aggregate<64, 0><<<AGB, 256>>>(h, agg);                              // 3
    k_gemm<64, 8, 1, 3><<<GB, 256>>>(agg, W2, b2, h, g1, be1, 0);          // 4 (profiled)
    k_aggregate<64, 128><<<AGB, 256>>>(h, agg);                            // 5
    k_gemm<64, 5, 1, 3><<<GB, 256>>>(agg, W3, b3, h, g2, be2, 128);        // 6
    k_aggregate<40, -1><<<AGB, 256>>>(h, out);                             // 7
}